// round 4
// baseline (speedup 1.0000x reference)
#include <cuda_runtime.h>

// Problem constants
#define NB   8
#define SEQ  2048
#define DIM  1024
#define HS   64

// ---------------- scratch (no cudaMalloc allowed) ----------------
__device__ float g_q [NB * SEQ * HS];   // q * 0.125, row-major [b][s][h]
__device__ float g_kT[NB * HS * SEQ];   // k transposed    [b][h][s]
__device__ float g_v [NB * SEQ * HS];   // v row-major     [b][s][h]

// =================================================================
// Projection: C[16384,64] = X[16384,1024] @ W[1024,64]
// 128 threads, BM=128, 8x8 register tile (ty:16 rows-groups, tx:8 col-groups)
// =================================================================
#define PBM 128
#define PBK 16

__global__ __launch_bounds__(128, 4) void proj_kernel(
    const float* __restrict__ Xq, const float* __restrict__ Xk, const float* __restrict__ Xv,
    const float* __restrict__ Wq, const float* __restrict__ Wk, const float* __restrict__ Wv)
{
    const int mode = blockIdx.y;            // 0=q, 1=k(transposed out), 2=v
    const float* X;
    const float* W;
    if (mode == 0)      { X = Xq; W = Wq; }
    else if (mode == 1) { X = Xk; W = Wk; }
    else                { X = Xv; W = Wv; }

    __shared__ float At[PBK][PBM];          // A chunk, k-major
    __shared__ float Ws[PBK][HS];           // W chunk, k-major (native layout)

    const int tid = threadIdx.x;
    const int ty  = tid >> 3;               // 0..15  -> rows ty*8..+7
    const int tx  = tid & 7;                // 0..7   -> cols tx*8..+7
    const int row0 = blockIdx.x * PBM;

    float acc[8][8];
#pragma unroll
    for (int i = 0; i < 8; i++)
#pragma unroll
        for (int j = 0; j < 8; j++) acc[i][j] = 0.0f;

    for (int kb = 0; kb < DIM; kb += PBK) {
        // load A chunk (128x16) as float4, store transposed
#pragma unroll
        for (int t = tid; t < PBM * PBK / 4; t += 128) {
            int m  = t >> 2;
            int k4 = t & 3;
            float4 a = *(const float4*)(X + (size_t)(row0 + m) * DIM + kb + k4 * 4);
            At[k4 * 4 + 0][m] = a.x;
            At[k4 * 4 + 1][m] = a.y;
            At[k4 * 4 + 2][m] = a.z;
            At[k4 * 4 + 3][m] = a.w;
        }
        // load W chunk (16x64), native layout
#pragma unroll
        for (int t = tid; t < PBK * HS / 4; t += 128) {
            int kk = t >> 4;
            int n4 = t & 15;
            *(float4*)(&Ws[kk][n4 * 4]) =
                *(const float4*)(W + (size_t)(kb + kk) * HS + n4 * 4);
        }
        __syncthreads();

#pragma unroll
        for (int kk = 0; kk < PBK; kk++) {
            float a[8], w[8];
            *(float4*)(a)     = *(const float4*)(&At[kk][ty * 8]);
            *(float4*)(a + 4) = *(const float4*)(&At[kk][ty * 8 + 4]);
            *(float4*)(w)     = *(const float4*)(&Ws[kk][tx * 8]);
            *(float4*)(w + 4) = *(const float4*)(&Ws[kk][tx * 8 + 4]);
#pragma unroll
            for (int i = 0; i < 8; i++)
#pragma unroll
                for (int j = 0; j < 8; j++)
                    acc[i][j] += a[i] * w[j];
        }
        __syncthreads();
    }

    if (mode == 1) {
        // K stored transposed: g_kT[b][h][s]
        const int b  = row0 / SEQ;           // 2048 % 128 == 0 -> block within one batch
        const int s0 = row0 % SEQ;
#pragma unroll
        for (int j = 0; j < 8; j++)
#pragma unroll
            for (int i = 0; i < 8; i++)
                g_kT[((size_t)b * HS + tx * 8 + j) * SEQ + s0 + ty * 8 + i] = acc[i][j];
    } else {
        float* out = (mode == 0) ? g_q : g_v;
        const float sc = (mode == 0) ? 0.125f : 1.0f;   // fold softmax scale into q
#pragma unroll
        for (int i = 0; i < 8; i++) {
            float4 v0 = make_float4(acc[i][0] * sc, acc[i][1] * sc, acc[i][2] * sc, acc[i][3] * sc);
            float4 v1 = make_float4(acc[i][4] * sc, acc[i][5] * sc, acc[i][6] * sc, acc[i][7] * sc);
            float* p = out + (size_t)(row0 + ty * 8 + i) * HS + tx * 8;
            *(float4*)(p)     = v0;
            *(float4*)(p + 4) = v1;
        }
    }
}

// =================================================================
// Flash attention (causal), fp32.
// Block = 256 threads, Q tile = 64 rows. Thread grid 16x16, 4x4 tiles.
// =================================================================
#define QSTRIDE 65
#define KSTRIDE 68
#define PSTRIDE 68
#define ATTN_SMEM ((64 * QSTRIDE + 64 * KSTRIDE + 64 * 64 + 64 * PSTRIDE) * (int)sizeof(float))

__global__ __launch_bounds__(256, 3) void attn_kernel(float* __restrict__ out)
{
    extern __shared__ float sm[];
    float* Qs = sm;                           // [64][65]  row-major [i][k] (pre-scaled)
    float* Kt = Qs + 64 * QSTRIDE;            // [64][68]  k-major  [h][j]
    float* Vs = Kt + 64 * KSTRIDE;            // [64][64]  row-major [j][h]
    float* Pt = Vs + 64 * 64;                 // [64][68]  row-major [i][j]

    const int b  = blockIdx.y;
    const int qt = (gridDim.x - 1) - blockIdx.x;   // longest (most KV tiles) first
    const int tid = threadIdx.x;
    const int ty = tid >> 4;                  // 0..15 -> rows i = ty*4..+3
    const int tx = tid & 15;                  // 0..15 -> cols j/h = tx*4..+3

    const float* Qg  = g_q  + ((size_t)b * SEQ + qt * 64) * HS;
    const float* KTg = g_kT + (size_t)b * HS * SEQ;
    const float* Vg  = g_v  + (size_t)b * SEQ * HS;

    // load Q tile (64x64), row-major, stride 65 (scalar stores keep banks clean)
#pragma unroll
    for (int t = tid; t < 64 * 16; t += 256) {
        int i  = t >> 4;
        int k4 = t & 15;
        float4 qv = *(const float4*)(Qg + (size_t)i * HS + k4 * 4);
        Qs[i * QSTRIDE + k4 * 4 + 0] = qv.x;
        Qs[i * QSTRIDE + k4 * 4 + 1] = qv.y;
        Qs[i * QSTRIDE + k4 * 4 + 2] = qv.z;
        Qs[i * QSTRIDE + k4 * 4 + 3] = qv.w;
    }

    float o[4][4];
    float m[4], l[4];
#pragma unroll
    for (int a = 0; a < 4; a++) {
        m[a] = -1e30f;
        l[a] = 0.0f;
#pragma unroll
        for (int c = 0; c < 4; c++) o[a][c] = 0.0f;
    }

    for (int kt = 0; kt <= qt; kt++) {
        __syncthreads();   // prior reads of Kt/Vs/Pt done; Qs store visible (kt==0)

        // K tile: direct copy from transposed K, float4 both sides
#pragma unroll
        for (int t = tid; t < 64 * 16; t += 256) {
            int h  = t >> 4;
            int j4 = t & 15;
            *(float4*)(&Kt[h * KSTRIDE + j4 * 4]) =
                *(const float4*)(KTg + (size_t)h * SEQ + kt * 64 + j4 * 4);
        }
        // V tile: direct copy, row-major
#pragma unroll
        for (int t = tid; t < 64 * 16; t += 256) {
            int j  = t >> 4;
            int h4 = t & 15;
            *(float4*)(&Vs[j * 64 + h4 * 4]) =
                *(const float4*)(Vg + (size_t)(kt * 64 + j) * HS + h4 * 4);
        }
        __syncthreads();

        // S = Q @ K^T  (scale already folded into Q)
        float s[4][4];
#pragma unroll
        for (int a = 0; a < 4; a++)
#pragma unroll
            for (int c = 0; c < 4; c++) s[a][c] = 0.0f;

#pragma unroll
        for (int kk = 0; kk < HS; kk++) {
            float q0 = Qs[(ty * 4 + 0) * QSTRIDE + kk];
            float q1 = Qs[(ty * 4 + 1) * QSTRIDE + kk];
            float q2 = Qs[(ty * 4 + 2) * QSTRIDE + kk];
            float q3 = Qs[(ty * 4 + 3) * QSTRIDE + kk];
            float4 kv = *(const float4*)(&Kt[kk * KSTRIDE + tx * 4]);
            s[0][0] += q0 * kv.x; s[0][1] += q0 * kv.y; s[0][2] += q0 * kv.z; s[0][3] += q0 * kv.w;
            s[1][0] += q1 * kv.x; s[1][1] += q1 * kv.y; s[1][2] += q1 * kv.z; s[1][3] += q1 * kv.w;
            s[2][0] += q2 * kv.x; s[2][1] += q2 * kv.y; s[2][2] += q2 * kv.z; s[2][3] += q2 * kv.w;
            s[3][0] += q3 * kv.x; s[3][1] += q3 * kv.y; s[3][2] += q3 * kv.z; s[3][3] += q3 * kv.w;
        }

        // causal mask (only the diagonal tile)
        if (kt == qt) {
#pragma unroll
            for (int a = 0; a < 4; a++)
#pragma unroll
                for (int c = 0; c < 4; c++)
                    if (tx * 4 + c > ty * 4 + a) s[a][c] = -1e30f;
        }

        // online softmax: row stats across the 16 tx lanes of each ty group
#pragma unroll
        for (int a = 0; a < 4; a++) {
            float rm = fmaxf(fmaxf(s[a][0], s[a][1]), fmaxf(s[a][2], s[a][3]));
            rm = fmaxf(rm, __shfl_xor_sync(0xffffffffu, rm, 1));
            rm = fmaxf(rm, __shfl_xor_sync(0xffffffffu, rm, 2));
            rm = fmaxf(rm, __shfl_xor_sync(0xffffffffu, rm, 4));
            rm = fmaxf(rm, __shfl_xor_sync(0xffffffffu, rm, 8));
            float mnew  = fmaxf(m[a], rm);
            float alpha = __expf(m[a] - mnew);
            m[a] = mnew;

            float rs = 0.0f;
#pragma unroll
            for (int c = 0; c < 4; c++) {
                s[a][c] = __expf(s[a][c] - mnew);
                rs += s[a][c];
            }
            rs += __shfl_xor_sync(0xffffffffu, rs, 1);
            rs += __shfl_xor_sync(0xffffffffu, rs, 2);
            rs += __shfl_xor_sync(0xffffffffu, rs, 4);
            rs += __shfl_xor_sync(0xffffffffu, rs, 8);
            l[a] = l[a] * alpha + rs;
#pragma unroll
            for (int c = 0; c < 4; c++) o[a][c] *= alpha;
        }

        // stage P into smem ([i][j], float4 stores)
#pragma unroll
        for (int a = 0; a < 4; a++)
            *(float4*)(&Pt[(ty * 4 + a) * PSTRIDE + tx * 4]) =
                make_float4(s[a][0], s[a][1], s[a][2], s[a][3]);
        __syncthreads();

        // O += P @ V   (i = ty*4..+3, h = tx*4..+3)
#pragma unroll
        for (int jj = 0; jj < 64; jj++) {
            float p0 = Pt[(ty * 4 + 0) * PSTRIDE + jj];
            float p1 = Pt[(ty * 4 + 1) * PSTRIDE + jj];
            float p2 = Pt[(ty * 4 + 2) * PSTRIDE + jj];
            float p3 = Pt[(ty * 4 + 3) * PSTRIDE + jj];
            float4 vv = *(const float4*)(&Vs[jj * 64 + tx * 4]);
            o[0][0] += p0 * vv.x; o[0][1] += p0 * vv.y; o[0][2] += p0 * vv.z; o[0][3] += p0 * vv.w;
            o[1][0] += p1 * vv.x; o[1][1] += p1 * vv.y; o[1][2] += p1 * vv.z; o[1][3] += p1 * vv.w;
            o[2][0] += p2 * vv.x; o[2][1] += p2 * vv.y; o[2][2] += p2 * vv.z; o[2][3] += p2 * vv.w;
            o[3][0] += p3 * vv.x; o[3][1] += p3 * vv.y; o[3][2] += p3 * vv.z; o[3][3] += p3 * vv.w;
        }
    }

    // epilogue: normalize and store
#pragma unroll
    for (int a = 0; a < 4; a++) {
        float inv = 1.0f / l[a];
        float4 r = make_float4(o[a][0] * inv, o[a][1] * inv, o[a][2] * inv, o[a][3] * inv);
        *(float4*)(out + ((size_t)b * SEQ + qt * 64 + ty * 4 + a) * HS + tx * 4) = r;
    }
}

// =================================================================
extern "C" void kernel_launch(void* const* d_in, const int* in_sizes, int n_in,
                              void* d_out, int out_size)
{
    (void)in_sizes; (void)n_in; (void)out_size;
    const float* query = (const float*)d_in[0];
    const float* key   = (const float*)d_in[1];
    const float* value = (const float*)d_in[2];
    const float* Wq    = (const float*)d_in[3];
    const float* Wk    = (const float*)d_in[4];
    const float* Wv    = (const float*)d_in[5];

    // q/k/v projections (k written transposed, q pre-scaled by 1/sqrt(HS))
    proj_kernel<<<dim3((NB * SEQ) / PBM, 3, 1), 128>>>(query, key, value, Wq, Wk, Wv);

    cudaFuncSetAttribute(attn_kernel, cudaFuncAttributeMaxDynamicSharedMemorySize, ATTN_SMEM);
    attn_kernel<<<dim3(SEQ / 64, NB, 1), 256, ATTN_SMEM>>>((float*)d_out);
}

// round 6
// speedup vs baseline: 2.4245x; 2.4245x over previous
#include <cuda_runtime.h>
#include <cuda_bf16.h>
#include <cstdint>

#define NB   8
#define SEQ  2048
#define DIM  1024
#define HS   64

// ---------------- device scratch (no cudaMalloc allowed) ----------------
__device__ __nv_bfloat16 g_qh [NB * SEQ * HS];   // q*0.125 hi, [b][s][h]
__device__ __nv_bfloat16 g_ql [NB * SEQ * HS];
__device__ __nv_bfloat16 g_kh [NB * SEQ * HS];   // k hi, [b][s][h]
__device__ __nv_bfloat16 g_kl [NB * SEQ * HS];
__device__ __nv_bfloat16 g_vth[NB * HS * SEQ];   // v^T hi: [b][h][s]
__device__ __nv_bfloat16 g_vtl[NB * HS * SEQ];
__device__ __nv_bfloat16 g_wth[3 * HS * DIM];    // W^T hi: [mode][n][k]
__device__ __nv_bfloat16 g_wtl[3 * HS * DIM];

// ---------------- helpers ----------------
__device__ __forceinline__ uint32_t s2u(const void* p) {
    uint32_t a;
    asm("{ .reg .u64 t; cvta.to.shared.u64 t, %1; cvt.u32.u64 %0, t; }" : "=r"(a) : "l"(p));
    return a;
}
__device__ __forceinline__ void fsplit(float a, __nv_bfloat16& h, __nv_bfloat16& l) {
    h = __float2bfloat16(a);
    l = __float2bfloat16(a - __bfloat162float(h));
}
__device__ __forceinline__ uint32_t pack2(__nv_bfloat16 a, __nv_bfloat16 b) {
    __nv_bfloat162 v = __halves2bfloat162(a, b);
    return *reinterpret_cast<uint32_t*>(&v);
}
__device__ __forceinline__ void ldsm4(uint32_t r[4], uint32_t addr) {
    asm volatile("ldmatrix.sync.aligned.m8n8.x4.shared.b16 {%0,%1,%2,%3}, [%4];"
                 : "=r"(r[0]), "=r"(r[1]), "=r"(r[2]), "=r"(r[3]) : "r"(addr));
}
__device__ __forceinline__ void mma_bf16(float d[4], const uint32_t a[4], const uint32_t b[2]) {
    asm volatile("mma.sync.aligned.m16n8k16.row.col.f32.bf16.bf16.f32 "
                 "{%0,%1,%2,%3},{%4,%5,%6,%7},{%8,%9},{%0,%1,%2,%3};"
                 : "+f"(d[0]), "+f"(d[1]), "+f"(d[2]), "+f"(d[3])
                 : "r"(a[0]), "r"(a[1]), "r"(a[2]), "r"(a[3]), "r"(b[0]), "r"(b[1]));
}
__device__ __forceinline__ void cpa16(uint32_t saddr, const void* gaddr) {
    asm volatile("cp.async.cg.shared.global [%0], [%1], 16;" :: "r"(saddr), "l"(gaddr));
}
#define CP_COMMIT() asm volatile("cp.async.commit_group;" ::: "memory")
#define CP_WAIT1()  asm volatile("cp.async.wait_group 1;" ::: "memory")
#define CP_WAIT0()  asm volatile("cp.async.wait_group 0;" ::: "memory")

// =================================================================
// Kernel 1: W -> W^T bf16 hi/lo (Wq pre-scaled by 0.125, exact pow2)
// =================================================================
__global__ void prep_w(const float* __restrict__ Wq, const float* __restrict__ Wk,
                       const float* __restrict__ Wv)
{
    int mode = blockIdx.y;
    const float* W = (mode == 0) ? Wq : ((mode == 1) ? Wk : Wv);
    float sc = (mode == 0) ? 0.125f : 1.0f;
    int t = blockIdx.x * 256 + threadIdx.x;      // 0..65535
    int k = t >> 6, n = t & 63;
    float x = W[(size_t)k * HS + n] * sc;
    __nv_bfloat16 h, l;
    fsplit(x, h, l);
    g_wth[((size_t)mode * HS + n) * DIM + k] = h;
    g_wtl[((size_t)mode * HS + n) * DIM + k] = l;
}

// =================================================================
// Kernel 2: projections via mma.sync bf16-split.
// Block 256 thr (8 warps), each warp m16 x n64. C[128,64] per block.
// =================================================================
#define PST 40   // smem row stride in halves (80B, coprime with banks)

__global__ __launch_bounds__(256) void proj_mma(
    const float* __restrict__ Xq, const float* __restrict__ Xk, const float* __restrict__ Xv)
{
    __shared__ __align__(16) __nv_bfloat16 sAh[128 * PST];
    __shared__ __align__(16) __nv_bfloat16 sAl[128 * PST];
    __shared__ __align__(16) __nv_bfloat16 sBh[64 * PST];
    __shared__ __align__(16) __nv_bfloat16 sBl[64 * PST];

    const int tid = threadIdx.x;
    const int lane = tid & 31, w = tid >> 5;
    const int mode = blockIdx.y;
    const int row0 = blockIdx.x * 128;

    const float* X = (mode == 0) ? Xq : ((mode == 1) ? Xk : Xv);
    const __nv_bfloat16* WTh = g_wth + (size_t)mode * HS * DIM;
    const __nv_bfloat16* WTl = g_wtl + (size_t)mode * HS * DIM;

    const uint32_t aBase = s2u(sAh), alBase = s2u(sAl);
    const uint32_t bBase = s2u(sBh), blBase = s2u(sBl);
    const uint32_t laneA = (uint32_t)((((lane & 7) + (((lane >> 3) & 1) << 3)) * PST + ((lane >> 4) << 3)) * 2);
    const uint32_t laneB = (uint32_t)((((lane & 7) + ((lane >> 4) << 3)) * PST + (((lane >> 3) & 1) << 3)) * 2);

    float acc[8][4];
#pragma unroll
    for (int nt = 0; nt < 8; nt++)
#pragma unroll
        for (int e = 0; e < 4; e++) acc[nt][e] = 0.0f;

    // register staging of next chunk (software pipeline)
    float4 fa[4];
    uint4 wbh, wbl;
    const int bn = tid >> 2, bq = tid & 3;

#pragma unroll
    for (int it = 0; it < 4; it++) {
        int idx = tid + it * 256, m = idx >> 3, kq = idx & 7;
        fa[it] = *(const float4*)(X + (size_t)(row0 + m) * DIM + kq * 4);
    }
    wbh = *(const uint4*)(WTh + (size_t)bn * DIM + bq * 8);
    wbl = *(const uint4*)(WTl + (size_t)bn * DIM + bq * 8);

    for (int kb = 0; kb < 32; kb++) {
        // store staged chunk into smem (convert A to bf16 hi/lo)
#pragma unroll
        for (int it = 0; it < 4; it++) {
            int idx = tid + it * 256, m = idx >> 3, kq = idx & 7;
            __nv_bfloat16 h0, h1, h2, h3, l0, l1, l2, l3;
            fsplit(fa[it].x, h0, l0); fsplit(fa[it].y, h1, l1);
            fsplit(fa[it].z, h2, l2); fsplit(fa[it].w, h3, l3);
            *(uint2*)(sAh + m * PST + kq * 4) = make_uint2(pack2(h0, h1), pack2(h2, h3));
            *(uint2*)(sAl + m * PST + kq * 4) = make_uint2(pack2(l0, l1), pack2(l2, l3));
        }
        *(uint4*)(sBh + bn * PST + bq * 8) = wbh;
        *(uint4*)(sBl + bn * PST + bq * 8) = wbl;
        __syncthreads();

        // prefetch next chunk
        if (kb + 1 < 32) {
            int kc = (kb + 1) * 32;
#pragma unroll
            for (int it = 0; it < 4; it++) {
                int idx = tid + it * 256, m = idx >> 3, kq = idx & 7;
                fa[it] = *(const float4*)(X + (size_t)(row0 + m) * DIM + kc + kq * 4);
            }
            wbh = *(const uint4*)(WTh + (size_t)bn * DIM + kc + bq * 8);
            wbl = *(const uint4*)(WTl + (size_t)bn * DIM + kc + bq * 8);
        }

#pragma unroll
        for (int ks = 0; ks < 2; ks++) {
            uint32_t ah[4], al_[4];
            ldsm4(ah,  aBase  + (uint32_t)((w * 16 * PST + ks * 16) * 2) + laneA);
            ldsm4(al_, alBase + (uint32_t)((w * 16 * PST + ks * 16) * 2) + laneA);
            uint32_t bh[16], bl[16];
#pragma unroll
            for (int p = 0; p < 4; p++) {
                ldsm4(&bh[p * 4], bBase  + (uint32_t)((p * 16 * PST + ks * 16) * 2) + laneB);
                ldsm4(&bl[p * 4], blBase + (uint32_t)((p * 16 * PST + ks * 16) * 2) + laneB);
            }
#pragma unroll
            for (int nt = 0; nt < 8; nt++) {
                const uint32_t* bph = &bh[(nt >> 1) * 4 + (nt & 1) * 2];
                const uint32_t* bpl = &bl[(nt >> 1) * 4 + (nt & 1) * 2];
                mma_bf16(acc[nt], ah, bph);
                mma_bf16(acc[nt], ah, bpl);
                mma_bf16(acc[nt], al_, bph);
            }
        }
        __syncthreads();
    }

    // epilogue: C-frag -> split bf16 global stores
    const int rl = row0 + w * 16 + (lane >> 2);
    if (mode == 2) {
        const int b = rl / SEQ, s = rl % SEQ;
#pragma unroll
        for (int nt = 0; nt < 8; nt++) {
            int c = nt * 8 + (lane & 3) * 2;
#pragma unroll
            for (int e = 0; e < 2; e++) {
                __nv_bfloat16 h, l;
                fsplit(acc[nt][e], h, l);
                g_vth[((size_t)b * HS + c + e) * SEQ + s] = h;
                g_vtl[((size_t)b * HS + c + e) * SEQ + s] = l;
                fsplit(acc[nt][2 + e], h, l);
                g_vth[((size_t)b * HS + c + e) * SEQ + s + 8] = h;
                g_vtl[((size_t)b * HS + c + e) * SEQ + s + 8] = l;
            }
        }
    } else {
        __nv_bfloat16* Oh = mode ? g_kh : g_qh;
        __nv_bfloat16* Ol = mode ? g_kl : g_ql;
#pragma unroll
        for (int nt = 0; nt < 8; nt++) {
            int c = nt * 8 + (lane & 3) * 2;
            __nv_bfloat16 h0, l0, h1, l1;
            fsplit(acc[nt][0], h0, l0); fsplit(acc[nt][1], h1, l1);
            *(uint32_t*)(Oh + (size_t)rl * HS + c) = pack2(h0, h1);
            *(uint32_t*)(Ol + (size_t)rl * HS + c) = pack2(l0, l1);
            fsplit(acc[nt][2], h0, l0); fsplit(acc[nt][3], h1, l1);
            *(uint32_t*)(Oh + (size_t)(rl + 8) * HS + c) = pack2(h0, h1);
            *(uint32_t*)(Ol + (size_t)(rl + 8) * HS + c) = pack2(l0, l1);
        }
    }
}

// =================================================================
// Kernel 3: causal flash attention via mma.sync bf16-split.
// Block 256 thr (8 warps), Q tile 128 rows (warp = m16), KV tiles 64,
// double-buffered cp.async. S and P live in MMA fragments.
// =================================================================
#define AST 72                        // smem row stride in halves (144B)
#define OFF_QH 0
#define OFF_QL 18432
#define OFF_BUF 36864
#define BUF_STRIDE 36864
#define ARR_STRIDE 9216               // 64*72*2 bytes per tile array
#define ATTN_SMEM 110592

__global__ __launch_bounds__(256, 1) void attn_mma(float* __restrict__ out)
{
    extern __shared__ __align__(16) char sm[];
    const uint32_t sb = s2u(sm);
    const int tid = threadIdx.x, lane = tid & 31, w = tid >> 5;
    const int b = blockIdx.y;
    const int qt = (int)(gridDim.x - 1) - (int)blockIdx.x;   // longest first
    const int nk = 2 * qt + 2;

    const __nv_bfloat16* Qh  = g_qh + ((size_t)b * SEQ + qt * 128) * HS;
    const __nv_bfloat16* Ql  = g_ql + ((size_t)b * SEQ + qt * 128) * HS;
    const __nv_bfloat16* Kh0 = g_kh + (size_t)b * SEQ * HS;
    const __nv_bfloat16* Kl0 = g_kl + (size_t)b * SEQ * HS;
    const __nv_bfloat16* Vh0 = g_vth + (size_t)b * HS * SEQ;
    const __nv_bfloat16* Vl0 = g_vtl + (size_t)b * HS * SEQ;

    // Q -> smem (plain)
#pragma unroll
    for (int it = 0; it < 4; it++) {
        int idx = tid + it * 256, r = idx >> 3, q = idx & 7;
        *(uint4*)(sm + OFF_QH + (r * AST + q * 8) * 2) = *(const uint4*)(Qh + (size_t)r * HS + q * 8);
        *(uint4*)(sm + OFF_QL + (r * AST + q * 8) * 2) = *(const uint4*)(Ql + (size_t)r * HS + q * 8);
    }

    auto issue_kv = [&](int kt, int dst) {
        uint32_t base = sb + OFF_BUF + dst * BUF_STRIDE;
#pragma unroll
        for (int it = 0; it < 8; it++) {
            int idx = tid + it * 256;            // 2048 chunks of 16B
            int a = idx >> 9, rem = idx & 511;
            int r = rem >> 3, q = rem & 7;
            const __nv_bfloat16* src;
            if (a == 0)      src = Kh0 + (size_t)(kt * 64 + r) * HS + q * 8;
            else if (a == 1) src = Kl0 + (size_t)(kt * 64 + r) * HS + q * 8;
            else if (a == 2) src = Vh0 + (size_t)r * SEQ + kt * 64 + q * 8;
            else             src = Vl0 + (size_t)r * SEQ + kt * 64 + q * 8;
            cpa16(base + a * ARR_STRIDE + (r * AST + q * 8) * 2, src);
        }
        CP_COMMIT();
    };
    issue_kv(0, 0);
    __syncthreads();                              // Q visible

    const uint32_t laneA = (uint32_t)((((lane & 7) + (((lane >> 3) & 1) << 3)) * AST + ((lane >> 4) << 3)) * 2);
    const uint32_t laneB = (uint32_t)((((lane & 7) + ((lane >> 4) << 3)) * AST + (((lane >> 3) & 1) << 3)) * 2);

    // Q fragments held in registers for the whole KV loop
    uint32_t qh[4][4], ql[4][4];
#pragma unroll
    for (int ks = 0; ks < 4; ks++) {
        ldsm4(qh[ks], sb + OFF_QH + (uint32_t)((w * 16 * AST + ks * 16) * 2) + laneA);
        ldsm4(ql[ks], sb + OFF_QL + (uint32_t)((w * 16 * AST + ks * 16) * 2) + laneA);
    }

    float O[8][4];
#pragma unroll
    for (int nt = 0; nt < 8; nt++)
#pragma unroll
        for (int e = 0; e < 4; e++) O[nt][e] = 0.0f;
    float mr0 = -1e30f, mr1 = -1e30f, lr0 = 0.0f, lr1 = 0.0f;

    for (int kt = 0; kt < nk; kt++) {
        const int bf = kt & 1;
        if (kt + 1 < nk) { issue_kv(kt + 1, bf ^ 1); CP_WAIT1(); }
        else             { CP_WAIT0(); }
        __syncthreads();                          // tile kt visible to all

        const uint32_t kbH = sb + OFF_BUF + bf * BUF_STRIDE;
        const uint32_t kbL = kbH + ARR_STRIDE;
        const uint32_t vbH = kbH + 2 * ARR_STRIDE;
        const uint32_t vbL = kbH + 3 * ARR_STRIDE;

        // ---- S = Q K^T (hh + hl + lh) ----
        float s[8][4];
#pragma unroll
        for (int nt = 0; nt < 8; nt++)
#pragma unroll
            for (int e = 0; e < 4; e++) s[nt][e] = 0.0f;

#pragma unroll
        for (int ks = 0; ks < 4; ks++) {
            uint32_t bh[16], bl[16];
#pragma unroll
            for (int p = 0; p < 4; p++) {
                ldsm4(&bh[p * 4], kbH + (uint32_t)((p * 16 * AST + ks * 16) * 2) + laneB);
                ldsm4(&bl[p * 4], kbL + (uint32_t)((p * 16 * AST + ks * 16) * 2) + laneB);
            }
#pragma unroll
            for (int nt = 0; nt < 8; nt++) {
                const uint32_t* bph = &bh[(nt >> 1) * 4 + (nt & 1) * 2];
                const uint32_t* bpl = &bl[(nt >> 1) * 4 + (nt & 1) * 2];
                mma_bf16(s[nt], qh[ks], bph);
                mma_bf16(s[nt], qh[ks], bpl);
                mma_bf16(s[nt], ql[ks], bph);
            }
        }

        // ---- causal mask (only the two diagonal tiles) ----
        if (kt >= 2 * qt) {
            int lim = qt * 128 + w * 16 + (lane >> 2) - kt * 64;
#pragma unroll
            for (int nt = 0; nt < 8; nt++) {
                int c = nt * 8 + (lane & 3) * 2;
                if (c     > lim)     s[nt][0] = -1e30f;
                if (c + 1 > lim)     s[nt][1] = -1e30f;
                if (c     > lim + 8) s[nt][2] = -1e30f;
                if (c + 1 > lim + 8) s[nt][3] = -1e30f;
            }
        }

        // ---- online softmax (two rows per thread, quad shfl reduce) ----
        float rm0 = -1e30f, rm1 = -1e30f;
#pragma unroll
        for (int nt = 0; nt < 8; nt++) {
            rm0 = fmaxf(rm0, fmaxf(s[nt][0], s[nt][1]));
            rm1 = fmaxf(rm1, fmaxf(s[nt][2], s[nt][3]));
        }
        rm0 = fmaxf(rm0, __shfl_xor_sync(0xffffffffu, rm0, 1));
        rm0 = fmaxf(rm0, __shfl_xor_sync(0xffffffffu, rm0, 2));
        rm1 = fmaxf(rm1, __shfl_xor_sync(0xffffffffu, rm1, 1));
        rm1 = fmaxf(rm1, __shfl_xor_sync(0xffffffffu, rm1, 2));
        float mn0 = fmaxf(mr0, rm0), mn1 = fmaxf(mr1, rm1);
        float al0 = __expf(mr0 - mn0), al1 = __expf(mr1 - mn1);
        mr0 = mn0; mr1 = mn1;

        float rs0 = 0.0f, rs1 = 0.0f;
#pragma unroll
        for (int nt = 0; nt < 8; nt++) {
            s[nt][0] = __expf(s[nt][0] - mn0);
            s[nt][1] = __expf(s[nt][1] - mn0);
            s[nt][2] = __expf(s[nt][2] - mn1);
            s[nt][3] = __expf(s[nt][3] - mn1);
            rs0 += s[nt][0] + s[nt][1];
            rs1 += s[nt][2] + s[nt][3];
        }
        rs0 += __shfl_xor_sync(0xffffffffu, rs0, 1);
        rs0 += __shfl_xor_sync(0xffffffffu, rs0, 2);
        rs1 += __shfl_xor_sync(0xffffffffu, rs1, 1);
        rs1 += __shfl_xor_sync(0xffffffffu, rs1, 2);
        lr0 = lr0 * al0 + rs0;
        lr1 = lr1 * al1 + rs1;
#pragma unroll
        for (int nt = 0; nt < 8; nt++) {
            O[nt][0] *= al0; O[nt][1] *= al0;
            O[nt][2] *= al1; O[nt][3] *= al1;
        }

        // ---- P (C-frag) -> A-frag bf16 hi/lo, in registers ----
        uint32_t ph[4][4], pl[4][4];
#pragma unroll
        for (int ks = 0; ks < 4; ks++) {
            int t0 = 2 * ks, t1 = 2 * ks + 1;
            __nv_bfloat16 ha, la, hb, lb;
            fsplit(s[t0][0], ha, la); fsplit(s[t0][1], hb, lb);
            ph[ks][0] = pack2(ha, hb); pl[ks][0] = pack2(la, lb);
            fsplit(s[t0][2], ha, la); fsplit(s[t0][3], hb, lb);
            ph[ks][1] = pack2(ha, hb); pl[ks][1] = pack2(la, lb);
            fsplit(s[t1][0], ha, la); fsplit(s[t1][1], hb, lb);
            ph[ks][2] = pack2(ha, hb); pl[ks][2] = pack2(la, lb);
            fsplit(s[t1][2], ha, la); fsplit(s[t1][3], hb, lb);
            ph[ks][3] = pack2(ha, hb); pl[ks][3] = pack2(la, lb);
        }

        // ---- O += P @ V (hh + hl + lh) ----
#pragma unroll
        for (int ks = 0; ks < 4; ks++) {
            uint32_t vh[16], vl[16];
#pragma unroll
            for (int p = 0; p < 4; p++) {
                ldsm4(&vh[p * 4], vbH + (uint32_t)((p * 16 * AST + ks * 16) * 2) + laneB);
                ldsm4(&vl[p * 4], vbL + (uint32_t)((p * 16 * AST + ks * 16) * 2) + laneB);
            }
#pragma unroll
            for (int nt = 0; nt < 8; nt++) {
                const uint32_t* vph = &vh[(nt >> 1) * 4 + (nt & 1) * 2];
                const uint32_t* vpl = &vl[(nt >> 1) * 4 + (nt & 1) * 2];
                mma_bf16(O[nt], ph[ks], vph);
                mma_bf16(O[nt], pl[ks], vph);
                mma_bf16(O[nt], ph[ks], vpl);
            }
        }
        __syncthreads();                          // all reads of buf bf done
    }

    // ---- epilogue ----
    float inv0 = 1.0f / lr0, inv1 = 1.0f / lr1;
    int i0 = qt * 128 + w * 16 + (lane >> 2);
    float* o0 = out + ((size_t)b * SEQ + i0) * HS;
    float* o1 = o0 + 8 * HS;
#pragma unroll
    for (int nt = 0; nt < 8; nt++) {
        int c = nt * 8 + (lane & 3) * 2;
        *(float2*)(o0 + c) = make_float2(O[nt][0] * inv0, O[nt][1] * inv0);
        *(float2*)(o1 + c) = make_float2(O[nt][2] * inv1, O[nt][3] * inv1);
    }
}

// =================================================================
extern "C" void kernel_launch(void* const* d_in, const int* in_sizes, int n_in,
                              void* d_out, int out_size)
{
    (void)in_sizes; (void)n_in; (void)out_size;
    const float* query = (const float*)d_in[0];
    const float* key   = (const float*)d_in[1];
    const float* value = (const float*)d_in[2];
    const float* Wq    = (const float*)d_in[3];
    const float* Wk    = (const float*)d_in[4];
    const float* Wv    = (const float*)d_in[5];

    prep_w<<<dim3(256, 3, 1), 256>>>(Wq, Wk, Wv);

    proj_mma<<<dim3(128, 3, 1), 256>>>(query, key, value);

    cudaFuncSetAttribute(attn_mma, cudaFuncAttributeMaxDynamicSharedMemorySize, ATTN_SMEM);
    attn_mma<<<dim3(16, NB, 1), 256, ATTN_SMEM>>>((float*)d_out);
}

// round 7
// speedup vs baseline: 2.6628x; 1.0983x over previous
#include <cuda_runtime.h>
#include <cuda_bf16.h>
#include <cstdint>

#define NB   8
#define SEQ  2048
#define DIM  1024
#define HS   64

// ---------------- device scratch (no cudaMalloc allowed) ----------------
__device__ __nv_bfloat16 g_qh [NB * SEQ * HS];   // q*(0.125*log2e) hi, [b][s][h]
__device__ __nv_bfloat16 g_ql [NB * SEQ * HS];
__device__ __nv_bfloat16 g_kh [NB * SEQ * HS];   // k hi, [b][s][h]
__device__ __nv_bfloat16 g_kl [NB * SEQ * HS];
__device__ __nv_bfloat16 g_vth[NB * HS * SEQ];   // v^T hi: [b][h][s]
__device__ __nv_bfloat16 g_vtl[NB * HS * SEQ];
__device__ __nv_bfloat16 g_wth[3 * HS * DIM];    // W^T hi: [mode][n][k]
__device__ __nv_bfloat16 g_wtl[3 * HS * DIM];

// split-KV partials: 2 halves per (b, qtile)
#define NPART (NB * 16 * 2)
__device__ float g_pO[NPART][128][64];           // unnormalized partial O
__device__ float g_pm[NPART][128];               // row max (log2 domain)
__device__ float g_pl[NPART][128];               // row sum

// ---------------- helpers ----------------
__device__ __forceinline__ uint32_t s2u(const void* p) {
    uint32_t a;
    asm("{ .reg .u64 t; cvta.to.shared.u64 t, %1; cvt.u32.u64 %0, t; }" : "=r"(a) : "l"(p));
    return a;
}
__device__ __forceinline__ void fsplit(float a, __nv_bfloat16& h, __nv_bfloat16& l) {
    h = __float2bfloat16(a);
    l = __float2bfloat16(a - __bfloat162float(h));
}
__device__ __forceinline__ uint32_t pack2(__nv_bfloat16 a, __nv_bfloat16 b) {
    __nv_bfloat162 v = __halves2bfloat162(a, b);
    return *reinterpret_cast<uint32_t*>(&v);
}
__device__ __forceinline__ float ex2(float x) {
    float y;
    asm("ex2.approx.f32 %0, %1;" : "=f"(y) : "f"(x));
    return y;
}
__device__ __forceinline__ void ldsm4(uint32_t r[4], uint32_t addr) {
    asm volatile("ldmatrix.sync.aligned.m8n8.x4.shared.b16 {%0,%1,%2,%3}, [%4];"
                 : "=r"(r[0]), "=r"(r[1]), "=r"(r[2]), "=r"(r[3]) : "r"(addr));
}
__device__ __forceinline__ void mma_bf16(float d[4], const uint32_t a[4], const uint32_t b[2]) {
    asm volatile("mma.sync.aligned.m16n8k16.row.col.f32.bf16.bf16.f32 "
                 "{%0,%1,%2,%3},{%4,%5,%6,%7},{%8,%9},{%0,%1,%2,%3};"
                 : "+f"(d[0]), "+f"(d[1]), "+f"(d[2]), "+f"(d[3])
                 : "r"(a[0]), "r"(a[1]), "r"(a[2]), "r"(a[3]), "r"(b[0]), "r"(b[1]));
}
__device__ __forceinline__ void cpa16(uint32_t saddr, const void* gaddr) {
    asm volatile("cp.async.cg.shared.global [%0], [%1], 16;" :: "r"(saddr), "l"(gaddr));
}
#define CP_COMMIT() asm volatile("cp.async.commit_group;" ::: "memory")
#define CP_WAIT1()  asm volatile("cp.async.wait_group 1;" ::: "memory")
#define CP_WAIT0()  asm volatile("cp.async.wait_group 0;" ::: "memory")

// =================================================================
// Kernel 1: W -> W^T bf16 hi/lo. Wq pre-scaled by 0.125*log2(e)
// (exp2 domain). Adjacent threads handle adjacent k -> coalesced writes.
// =================================================================
__global__ void prep_w(const float* __restrict__ Wq, const float* __restrict__ Wk,
                       const float* __restrict__ Wv)
{
    int mode = blockIdx.y;
    const float* W = (mode == 0) ? Wq : ((mode == 1) ? Wk : Wv);
    float sc = (mode == 0) ? 0.18033688011112042f : 1.0f;   // 0.125 * log2(e)
    int t = blockIdx.x * 256 + threadIdx.x;      // 0..65535
    int k = t & 1023, n = t >> 10;
    float x = W[(size_t)k * HS + n] * sc;
    __nv_bfloat16 h, l;
    fsplit(x, h, l);
    g_wth[((size_t)mode * HS + n) * DIM + k] = h;
    g_wtl[((size_t)mode * HS + n) * DIM + k] = l;
}

// =================================================================
// Kernel 2: projections via mma.sync bf16-split (unchanged from R6).
// =================================================================
#define PST 40

__global__ __launch_bounds__(256) void proj_mma(
    const float* __restrict__ Xq, const float* __restrict__ Xk, const float* __restrict__ Xv)
{
    __shared__ __align__(16) __nv_bfloat16 sAh[128 * PST];
    __shared__ __align__(16) __nv_bfloat16 sAl[128 * PST];
    __shared__ __align__(16) __nv_bfloat16 sBh[64 * PST];
    __shared__ __align__(16) __nv_bfloat16 sBl[64 * PST];

    const int tid = threadIdx.x;
    const int lane = tid & 31, w = tid >> 5;
    const int mode = blockIdx.y;
    const int row0 = blockIdx.x * 128;

    const float* X = (mode == 0) ? Xq : ((mode == 1) ? Xk : Xv);
    const __nv_bfloat16* WTh = g_wth + (size_t)mode * HS * DIM;
    const __nv_bfloat16* WTl = g_wtl + (size_t)mode * HS * DIM;

    const uint32_t aBase = s2u(sAh), alBase = s2u(sAl);
    const uint32_t bBase = s2u(sBh), blBase = s2u(sBl);
    const uint32_t laneA = (uint32_t)((((lane & 7) + (((lane >> 3) & 1) << 3)) * PST + ((lane >> 4) << 3)) * 2);
    const uint32_t laneB = (uint32_t)((((lane & 7) + ((lane >> 4) << 3)) * PST + (((lane >> 3) & 1) << 3)) * 2);

    float acc[8][4];
#pragma unroll
    for (int nt = 0; nt < 8; nt++)
#pragma unroll
        for (int e = 0; e < 4; e++) acc[nt][e] = 0.0f;

    float4 fa[4];
    uint4 wbh, wbl;
    const int bn = tid >> 2, bq = tid & 3;

#pragma unroll
    for (int it = 0; it < 4; it++) {
        int idx = tid + it * 256, m = idx >> 3, kq = idx & 7;
        fa[it] = *(const float4*)(X + (size_t)(row0 + m) * DIM + kq * 4);
    }
    wbh = *(const uint4*)(WTh + (size_t)bn * DIM + bq * 8);
    wbl = *(const uint4*)(WTl + (size_t)bn * DIM + bq * 8);

    for (int kb = 0; kb < 32; kb++) {
#pragma unroll
        for (int it = 0; it < 4; it++) {
            int idx = tid + it * 256, m = idx >> 3, kq = idx & 7;
            __nv_bfloat16 h0, h1, h2, h3, l0, l1, l2, l3;
            fsplit(fa[it].x, h0, l0); fsplit(fa[it].y, h1, l1);
            fsplit(fa[it].z, h2, l2); fsplit(fa[it].w, h3, l3);
            *(uint2*)(sAh + m * PST + kq * 4) = make_uint2(pack2(h0, h1), pack2(h2, h3));
            *(uint2*)(sAl + m * PST + kq * 4) = make_uint2(pack2(l0, l1), pack2(l2, l3));
        }
        *(uint4*)(sBh + bn * PST + bq * 8) = wbh;
        *(uint4*)(sBl + bn * PST + bq * 8) = wbl;
        __syncthreads();

        if (kb + 1 < 32) {
            int kc = (kb + 1) * 32;
#pragma unroll
            for (int it = 0; it < 4; it++) {
                int idx = tid + it * 256, m = idx >> 3, kq = idx & 7;
                fa[it] = *(const float4*)(X + (size_t)(row0 + m) * DIM + kc + kq * 4);
            }
            wbh = *(const uint4*)(WTh + (size_t)bn * DIM + kc + bq * 8);
            wbl = *(const uint4*)(WTl + (size_t)bn * DIM + kc + bq * 8);
        }

#pragma unroll
        for (int ks = 0; ks < 2; ks++) {
            uint32_t ah[4], al_[4];
            ldsm4(ah,  aBase  + (uint32_t)((w * 16 * PST + ks * 16) * 2) + laneA);
            ldsm4(al_, alBase + (uint32_t)((w * 16 * PST + ks * 16) * 2) + laneA);
            uint32_t bh[16], bl[16];
#pragma unroll
            for (int p = 0; p < 4; p++) {
                ldsm4(&bh[p * 4], bBase  + (uint32_t)((p * 16 * PST + ks * 16) * 2) + laneB);
                ldsm4(&bl[p * 4], blBase + (uint32_t)((p * 16 * PST + ks * 16) * 2) + laneB);
            }
#pragma unroll
            for (int nt = 0; nt < 8; nt++) {
                const uint32_t* bph = &bh[(nt >> 1) * 4 + (nt & 1) * 2];
                const uint32_t* bpl = &bl[(nt >> 1) * 4 + (nt & 1) * 2];
                mma_bf16(acc[nt], ah, bph);
                mma_bf16(acc[nt], ah, bpl);
                mma_bf16(acc[nt], al_, bph);
            }
        }
        __syncthreads();
    }

    const int rl = row0 + w * 16 + (lane >> 2);
    if (mode == 2) {
        const int b = rl / SEQ, s = rl % SEQ;
#pragma unroll
        for (int nt = 0; nt < 8; nt++) {
            int c = nt * 8 + (lane & 3) * 2;
#pragma unroll
            for (int e = 0; e < 2; e++) {
                __nv_bfloat16 h, l;
                fsplit(acc[nt][e], h, l);
                g_vth[((size_t)b * HS + c + e) * SEQ + s] = h;
                g_vtl[((size_t)b * HS + c + e) * SEQ + s] = l;
                fsplit(acc[nt][2 + e], h, l);
                g_vth[((size_t)b * HS + c + e) * SEQ + s + 8] = h;
                g_vtl[((size_t)b * HS + c + e) * SEQ + s + 8] = l;
            }
        }
    } else {
        __nv_bfloat16* Oh = mode ? g_kh : g_qh;
        __nv_bfloat16* Ol = mode ? g_kl : g_ql;
#pragma unroll
        for (int nt = 0; nt < 8; nt++) {
            int c = nt * 8 + (lane & 3) * 2;
            __nv_bfloat16 h0, l0, h1, l1;
            fsplit(acc[nt][0], h0, l0); fsplit(acc[nt][1], h1, l1);
            *(uint32_t*)(Oh + (size_t)rl * HS + c) = pack2(h0, h1);
            *(uint32_t*)(Ol + (size_t)rl * HS + c) = pack2(l0, l1);
            fsplit(acc[nt][2], h0, l0); fsplit(acc[nt][3], h1, l1);
            *(uint32_t*)(Oh + (size_t)(rl + 8) * HS + c) = pack2(h0, h1);
            *(uint32_t*)(Ol + (size_t)(rl + 8) * HS + c) = pack2(l0, l1);
        }
    }
}

// =================================================================
// Kernel 3: split-KV causal flash attention via mma.sync bf16-split.
// Grid (32, NB): x -> (qt = 15 - (x>>1), half = x&1). Each block does
// half the KV range of its q-tile and writes unnormalized (O, m, l).
// =================================================================
#define AST 72
#define OFF_QH 0
#define OFF_QL 18432
#define OFF_BUF 36864
#define BUF_STRIDE 36864
#define ARR_STRIDE 9216
#define ATTN_SMEM 110592

__global__ __launch_bounds__(256, 1) void attn_mma()
{
    extern __shared__ __align__(16) char sm[];
    const uint32_t sb = s2u(sm);
    const int tid = threadIdx.x, lane = tid & 31, w = tid >> 5;
    const int b = blockIdx.y;
    const int qt   = 15 - ((int)blockIdx.x >> 1);    // longest first
    const int half = (int)blockIdx.x & 1;
    const int k0 = half ? (qt + 1) : 0;              // KV tile range [k0, k1)
    const int k1 = half ? (2 * qt + 2) : (qt + 1);
    const int part = ((b * 16 + qt) * 2) + half;

    const __nv_bfloat16* Qh  = g_qh + ((size_t)b * SEQ + qt * 128) * HS;
    const __nv_bfloat16* Ql  = g_ql + ((size_t)b * SEQ + qt * 128) * HS;
    const __nv_bfloat16* Kh0 = g_kh + (size_t)b * SEQ * HS;
    const __nv_bfloat16* Kl0 = g_kl + (size_t)b * SEQ * HS;
    const __nv_bfloat16* Vh0 = g_vth + (size_t)b * HS * SEQ;
    const __nv_bfloat16* Vl0 = g_vtl + (size_t)b * HS * SEQ;

#pragma unroll
    for (int it = 0; it < 4; it++) {
        int idx = tid + it * 256, r = idx >> 3, q = idx & 7;
        *(uint4*)(sm + OFF_QH + (r * AST + q * 8) * 2) = *(const uint4*)(Qh + (size_t)r * HS + q * 8);
        *(uint4*)(sm + OFF_QL + (r * AST + q * 8) * 2) = *(const uint4*)(Ql + (size_t)r * HS + q * 8);
    }

    auto issue_kv = [&](int kt, int dst) {
        uint32_t base = sb + OFF_BUF + dst * BUF_STRIDE;
#pragma unroll
        for (int it = 0; it < 8; it++) {
            int idx = tid + it * 256;
            int a = idx >> 9, rem = idx & 511;
            int r = rem >> 3, q = rem & 7;
            const __nv_bfloat16* src;
            if (a == 0)      src = Kh0 + (size_t)(kt * 64 + r) * HS + q * 8;
            else if (a == 1) src = Kl0 + (size_t)(kt * 64 + r) * HS + q * 8;
            else if (a == 2) src = Vh0 + (size_t)r * SEQ + kt * 64 + q * 8;
            else             src = Vl0 + (size_t)r * SEQ + kt * 64 + q * 8;
            cpa16(base + a * ARR_STRIDE + (r * AST + q * 8) * 2, src);
        }
        CP_COMMIT();
    };
    issue_kv(k0, 0);
    __syncthreads();

    const uint32_t laneA = (uint32_t)((((lane & 7) + (((lane >> 3) & 1) << 3)) * AST + ((lane >> 4) << 3)) * 2);
    const uint32_t laneB = (uint32_t)((((lane & 7) + ((lane >> 4) << 3)) * AST + (((lane >> 3) & 1) << 3)) * 2);

    uint32_t qh[4][4], ql[4][4];
#pragma unroll
    for (int ks = 0; ks < 4; ks++) {
        ldsm4(qh[ks], sb + OFF_QH + (uint32_t)((w * 16 * AST + ks * 16) * 2) + laneA);
        ldsm4(ql[ks], sb + OFF_QL + (uint32_t)((w * 16 * AST + ks * 16) * 2) + laneA);
    }

    float O[8][4];
#pragma unroll
    for (int nt = 0; nt < 8; nt++)
#pragma unroll
        for (int e = 0; e < 4; e++) O[nt][e] = 0.0f;
    float mr0 = -1e30f, mr1 = -1e30f, lr0 = 0.0f, lr1 = 0.0f;

    for (int kt = k0; kt < k1; kt++) {
        const int bf = (kt - k0) & 1;
        if (kt + 1 < k1) { issue_kv(kt + 1, bf ^ 1); CP_WAIT1(); }
        else             { CP_WAIT0(); }
        __syncthreads();

        const uint32_t kbH = sb + OFF_BUF + bf * BUF_STRIDE;
        const uint32_t kbL = kbH + ARR_STRIDE;
        const uint32_t vbH = kbH + 2 * ARR_STRIDE;
        const uint32_t vbL = kbH + 3 * ARR_STRIDE;

        // ---- S = Q K^T (hh + hl + lh), log2-domain scores ----
        float s[8][4];
#pragma unroll
        for (int nt = 0; nt < 8; nt++)
#pragma unroll
            for (int e = 0; e < 4; e++) s[nt][e] = 0.0f;

#pragma unroll
        for (int ks = 0; ks < 4; ks++) {
            uint32_t bh[16], bl[16];
#pragma unroll
            for (int p = 0; p < 4; p++) {
                ldsm4(&bh[p * 4], kbH + (uint32_t)((p * 16 * AST + ks * 16) * 2) + laneB);
                ldsm4(&bl[p * 4], kbL + (uint32_t)((p * 16 * AST + ks * 16) * 2) + laneB);
            }
#pragma unroll
            for (int nt = 0; nt < 8; nt++) {
                const uint32_t* bph = &bh[(nt >> 1) * 4 + (nt & 1) * 2];
                const uint32_t* bpl = &bl[(nt >> 1) * 4 + (nt & 1) * 2];
                mma_bf16(s[nt], qh[ks], bph);
                mma_bf16(s[nt], qh[ks], bpl);
                mma_bf16(s[nt], ql[ks], bph);
            }
        }

        // ---- causal mask (diagonal tiles only) ----
        if (kt >= 2 * qt) {
            int lim = qt * 128 + w * 16 + (lane >> 2) - kt * 64;
#pragma unroll
            for (int nt = 0; nt < 8; nt++) {
                int c = nt * 8 + (lane & 3) * 2;
                if (c     > lim)     s[nt][0] = -1e30f;
                if (c + 1 > lim)     s[nt][1] = -1e30f;
                if (c     > lim + 8) s[nt][2] = -1e30f;
                if (c + 1 > lim + 8) s[nt][3] = -1e30f;
            }
        }

        // ---- online softmax (exp2 domain) ----
        float rm0 = -1e30f, rm1 = -1e30f;
#pragma unroll
        for (int nt = 0; nt < 8; nt++) {
            rm0 = fmaxf(rm0, fmaxf(s[nt][0], s[nt][1]));
            rm1 = fmaxf(rm1, fmaxf(s[nt][2], s[nt][3]));
        }
        rm0 = fmaxf(rm0, __shfl_xor_sync(0xffffffffu, rm0, 1));
        rm0 = fmaxf(rm0, __shfl_xor_sync(0xffffffffu, rm0, 2));
        rm1 = fmaxf(rm1, __shfl_xor_sync(0xffffffffu, rm1, 1));
        rm1 = fmaxf(rm1, __shfl_xor_sync(0xffffffffu, rm1, 2));
        float mn0 = fmaxf(mr0, rm0), mn1 = fmaxf(mr1, rm1);
        float al0 = ex2(mr0 - mn0), al1 = ex2(mr1 - mn1);
        mr0 = mn0; mr1 = mn1;

        float rs0 = 0.0f, rs1 = 0.0f;
#pragma unroll
        for (int nt = 0; nt < 8; nt++) {
            s[nt][0] = ex2(s[nt][0] - mn0);
            s[nt][1] = ex2(s[nt][1] - mn0);
            s[nt][2] = ex2(s[nt][2] - mn1);
            s[nt][3] = ex2(s[nt][3] - mn1);
            rs0 += s[nt][0] + s[nt][1];
            rs1 += s[nt][2] + s[nt][3];
        }
        rs0 += __shfl_xor_sync(0xffffffffu, rs0, 1);
        rs0 += __shfl_xor_sync(0xffffffffu, rs0, 2);
        rs1 += __shfl_xor_sync(0xffffffffu, rs1, 1);
        rs1 += __shfl_xor_sync(0xffffffffu, rs1, 2);
        lr0 = lr0 * al0 + rs0;
        lr1 = lr1 * al1 + rs1;
#pragma unroll
        for (int nt = 0; nt < 8; nt++) {
            O[nt][0] *= al0; O[nt][1] *= al0;
            O[nt][2] *= al1; O[nt][3] *= al1;
        }

        // ---- P (C-frag) -> A-frag bf16 hi/lo ----
        uint32_t ph[4][4], pl[4][4];
#pragma unroll
        for (int ks = 0; ks < 4; ks++) {
            int t0 = 2 * ks, t1 = 2 * ks + 1;
            __nv_bfloat16 ha, la, hb, lb;
            fsplit(s[t0][0], ha, la); fsplit(s[t0][1], hb, lb);
            ph[ks][0] = pack2(ha, hb); pl[ks][0] = pack2(la, lb);
            fsplit(s[t0][2], ha, la); fsplit(s[t0][3], hb, lb);
            ph[ks][1] = pack2(ha, hb); pl[ks][1] = pack2(la, lb);
            fsplit(s[t1][0], ha, la); fsplit(s[t1][1], hb, lb);
            ph[ks][2] = pack2(ha, hb); pl[ks][2] = pack2(la, lb);
            fsplit(s[t1][2], ha, la); fsplit(s[t1][3], hb, lb);
            ph[ks][3] = pack2(ha, hb); pl[ks][3] = pack2(la, lb);
        }

        // ---- O += P @ V (hh + hl + lh) ----
#pragma unroll
        for (int ks = 0; ks < 4; ks++) {
            uint32_t vh[16], vl[16];
#pragma unroll
            for (int p = 0; p < 4; p++) {
                ldsm4(&vh[p * 4], vbH + (uint32_t)((p * 16 * AST + ks * 16) * 2) + laneB);
                ldsm4(&vl[p * 4], vbL + (uint32_t)((p * 16 * AST + ks * 16) * 2) + laneB);
            }
#pragma unroll
            for (int nt = 0; nt < 8; nt++) {
                const uint32_t* vph = &vh[(nt >> 1) * 4 + (nt & 1) * 2];
                const uint32_t* vpl = &vl[(nt >> 1) * 4 + (nt & 1) * 2];
                mma_bf16(O[nt], ph[ks], vph);
                mma_bf16(O[nt], pl[ks], vph);
                mma_bf16(O[nt], ph[ks], vpl);
            }
        }
        __syncthreads();
    }

    // ---- epilogue: unnormalized partials to scratch ----
    int r0 = w * 16 + (lane >> 2);
#pragma unroll
    for (int nt = 0; nt < 8; nt++) {
        int c = nt * 8 + (lane & 3) * 2;
        *(float2*)(&g_pO[part][r0][c])     = make_float2(O[nt][0], O[nt][1]);
        *(float2*)(&g_pO[part][r0 + 8][c]) = make_float2(O[nt][2], O[nt][3]);
    }
    if ((lane & 3) == 0) {
        g_pm[part][r0] = mr0;     g_pl[part][r0] = lr0;
        g_pm[part][r0 + 8] = mr1; g_pl[part][r0 + 8] = lr1;
    }
}

// =================================================================
// Kernel 4: combine the two KV halves.
// Grid (NB*16) blocks x 128 threads; thread = one output row.
// =================================================================
__global__ __launch_bounds__(128) void combine(float* __restrict__ out)
{
    const int pair = blockIdx.x;             // b*16 + qt
    const int r = threadIdx.x;
    const int p0 = pair * 2, p1 = p0 + 1;

    float m0 = g_pm[p0][r], l0 = g_pl[p0][r];
    float m1 = g_pm[p1][r], l1 = g_pl[p1][r];
    float M  = fmaxf(m0, m1);
    float w0 = ex2(m0 - M), w1 = ex2(m1 - M);
    float inv = 1.0f / (w0 * l0 + w1 * l1);
    float c0 = w0 * inv, c1 = w1 * inv;

    const int b = pair >> 4, qt = pair & 15;
    float* op = out + ((size_t)b * SEQ + qt * 128 + r) * HS;
#pragma unroll
    for (int u = 0; u < 16; u++) {
        float4 a = *(const float4*)(&g_pO[p0][r][u * 4]);
        float4 d = *(const float4*)(&g_pO[p1][r][u * 4]);
        *(float4*)(op + u * 4) = make_float4(a.x * c0 + d.x * c1, a.y * c0 + d.y * c1,
                                             a.z * c0 + d.z * c1, a.w * c0 + d.w * c1);
    }
}

// =================================================================
extern "C" void kernel_launch(void* const* d_in, const int* in_sizes, int n_in,
                              void* d_out, int out_size)
{
    (void)in_sizes; (void)n_in; (void)out_size;
    const float* query = (const float*)d_in[0];
    const float* key   = (const float*)d_in[1];
    const float* value = (const float*)d_in[2];
    const float* Wq    = (const float*)d_in[3];
    const float* Wk    = (const float*)d_in[4];
    const float* Wv    = (const float*)d_in[5];

    prep_w<<<dim3(256, 3, 1), 256>>>(Wq, Wk, Wv);

    proj_mma<<<dim3(128, 3, 1), 256>>>(query, key, value);

    cudaFuncSetAttribute(attn_mma, cudaFuncAttributeMaxDynamicSharedMemorySize, ATTN_SMEM);
    attn_mma<<<dim3(32, NB, 1), 256, ATTN_SMEM>>>();

    combine<<<NB * 16, 128>>>((float*)d_out);
}